// round 1
// baseline (speedup 1.0000x reference)
#include <cuda_runtime.h>
#include <cuda_bf16.h>

// Problem constants (fixed by the reference: B=16, T=1024, D=1024, O=10; T==D required)
#define BB 16
#define TT 1024
#define DD 1024
#define OO 10

// Scratch (device globals: allocation-free per harness rules)
__device__ float g_scores[BB * OO * TT];   // [b][o][t] layout
__device__ float g_wx[BB * OO * TT];       // softmaxed, [b][o][i] layout

// ---------------------------------------------------------------------------
// Kernel 1: scores[b][o][t] = (logits[b,t,:] . W[o,:] + bias[o]) / OO
// Grid: (B*T)/32 = 512 blocks x 256 threads. Warp owns 4 rows.
// ---------------------------------------------------------------------------
__global__ __launch_bounds__(256) void k_scores(const float* __restrict__ logits,
                                                const float* __restrict__ W,
                                                const float* __restrict__ bias) {
    __shared__ float Wsm[OO][DD];   // 40 KB

    // Cooperative load of W into smem (2560 float4)
    {
        const float4* Wv = (const float4*)W;
        float4* Ws = (float4*)&Wsm[0][0];
        #pragma unroll
        for (int i = threadIdx.x; i < OO * DD / 4; i += 256)
            Ws[i] = Wv[i];
    }
    __syncthreads();

    const int warp = threadIdx.x >> 5;
    const int lane = threadIdx.x & 31;
    const int row0 = blockIdx.x * 32 + warp * 4;   // global row in [0, B*T)

    float acc[4][OO];
    #pragma unroll
    for (int r = 0; r < 4; r++)
        #pragma unroll
        for (int o = 0; o < OO; o++) acc[r][o] = 0.0f;

    for (int k = 0; k < DD / 128; k++) {
        const int d0 = k * 128 + lane * 4;
        float4 lg[4];
        #pragma unroll
        for (int r = 0; r < 4; r++)
            lg[r] = *(const float4*)&logits[(row0 + r) * DD + d0];
        #pragma unroll
        for (int o = 0; o < OO; o++) {
            const float4 w4 = *(const float4*)&Wsm[o][d0];
            #pragma unroll
            for (int r = 0; r < 4; r++) {
                acc[r][o] = fmaf(lg[r].x, w4.x, acc[r][o]);
                acc[r][o] = fmaf(lg[r].y, w4.y, acc[r][o]);
                acc[r][o] = fmaf(lg[r].z, w4.z, acc[r][o]);
                acc[r][o] = fmaf(lg[r].w, w4.w, acc[r][o]);
            }
        }
    }

    // Warp butterfly reduce each of the 40 partials
    #pragma unroll
    for (int r = 0; r < 4; r++)
        #pragma unroll
        for (int o = 0; o < OO; o++) {
            float v = acc[r][o];
            #pragma unroll
            for (int s = 16; s > 0; s >>= 1)
                v += __shfl_xor_sync(0xffffffffu, v, s);
            acc[r][o] = v;
        }

    if (lane == 0) {
        #pragma unroll
        for (int r = 0; r < 4; r++) {
            const int row = row0 + r;
            const int b = row / TT;
            const int t = row % TT;
            #pragma unroll
            for (int o = 0; o < OO; o++)
                g_scores[(b * OO + o) * TT + t] =
                    (acc[r][o] + bias[o]) * (1.0f / OO);
        }
    }
}

// ---------------------------------------------------------------------------
// Kernel 2: softmax over t for each (b,o). 160 blocks x 256 threads.
// Reads g_scores[ro][0..T), writes g_wx[ro][0..T).
// ---------------------------------------------------------------------------
__global__ __launch_bounds__(256) void k_softmax() {
    const int ro = blockIdx.x;                 // (b*OO + o)
    const int tid = threadIdx.x;
    const float4 v = ((const float4*)&g_scores[ro * TT])[tid];

    __shared__ float red[8];

    // max
    float m = fmaxf(fmaxf(v.x, v.y), fmaxf(v.z, v.w));
    #pragma unroll
    for (int s = 16; s > 0; s >>= 1)
        m = fmaxf(m, __shfl_xor_sync(0xffffffffu, m, s));
    if ((tid & 31) == 0) red[tid >> 5] = m;
    __syncthreads();
    float mall = red[0];
    #pragma unroll
    for (int i = 1; i < 8; i++) mall = fmaxf(mall, red[i]);
    __syncthreads();

    // exp + sum
    float4 e;
    e.x = __expf(v.x - mall);
    e.y = __expf(v.y - mall);
    e.z = __expf(v.z - mall);
    e.w = __expf(v.w - mall);
    float s4 = e.x + e.y + e.z + e.w;
    #pragma unroll
    for (int s = 16; s > 0; s >>= 1)
        s4 += __shfl_xor_sync(0xffffffffu, s4, s);
    if ((tid & 31) == 0) red[tid >> 5] = s4;
    __syncthreads();
    float sall = 0.0f;
    #pragma unroll
    for (int i = 0; i < 8; i++) sall += red[i];

    const float inv = 1.0f / sall;
    float4 w;
    w.x = e.x * inv; w.y = e.y * inv; w.z = e.z * inv; w.w = e.w * inv;
    ((float4*)&g_wx[ro * TT])[tid] = w;
}

// ---------------------------------------------------------------------------
// Kernel 3: out[b][o][t] = sum_i logits[b,t,i] * g_wx[b][o][i]
// Same structure as k_scores, per-batch weight from g_wx.
// ---------------------------------------------------------------------------
__global__ __launch_bounds__(256) void k_out(const float* __restrict__ logits,
                                             float* __restrict__ out) {
    __shared__ float Wsm[OO][DD];

    const int row0blk = blockIdx.x * 32;       // 32 rows per block, batch-aligned
    const int b = row0blk / TT;

    {
        const float4* Wv = (const float4*)&g_wx[b * OO * TT];
        float4* Ws = (float4*)&Wsm[0][0];
        #pragma unroll
        for (int i = threadIdx.x; i < OO * DD / 4; i += 256)
            Ws[i] = Wv[i];
    }
    __syncthreads();

    const int warp = threadIdx.x >> 5;
    const int lane = threadIdx.x & 31;
    const int row0 = row0blk + warp * 4;

    float acc[4][OO];
    #pragma unroll
    for (int r = 0; r < 4; r++)
        #pragma unroll
        for (int o = 0; o < OO; o++) acc[r][o] = 0.0f;

    for (int k = 0; k < DD / 128; k++) {
        const int d0 = k * 128 + lane * 4;
        float4 lg[4];
        #pragma unroll
        for (int r = 0; r < 4; r++)
            lg[r] = *(const float4*)&logits[(row0 + r) * DD + d0];
        #pragma unroll
        for (int o = 0; o < OO; o++) {
            const float4 w4 = *(const float4*)&Wsm[o][d0];
            #pragma unroll
            for (int r = 0; r < 4; r++) {
                acc[r][o] = fmaf(lg[r].x, w4.x, acc[r][o]);
                acc[r][o] = fmaf(lg[r].y, w4.y, acc[r][o]);
                acc[r][o] = fmaf(lg[r].z, w4.z, acc[r][o]);
                acc[r][o] = fmaf(lg[r].w, w4.w, acc[r][o]);
            }
        }
    }

    #pragma unroll
    for (int r = 0; r < 4; r++)
        #pragma unroll
        for (int o = 0; o < OO; o++) {
            float v = acc[r][o];
            #pragma unroll
            for (int s = 16; s > 0; s >>= 1)
                v += __shfl_xor_sync(0xffffffffu, v, s);
            acc[r][o] = v;
        }

    if (lane == 0) {
        #pragma unroll
        for (int r = 0; r < 4; r++) {
            const int row = row0 + r;
            const int t = row % TT;
            #pragma unroll
            for (int o = 0; o < OO; o++)
                out[(b * OO + o) * TT + t] = acc[r][o];
        }
    }
}

// ---------------------------------------------------------------------------
// Launch: inputs per metadata order: logits, decision(unused), W, b
// ---------------------------------------------------------------------------
extern "C" void kernel_launch(void* const* d_in, const int* in_sizes, int n_in,
                              void* d_out, int out_size) {
    const float* logits = (const float*)d_in[0];
    // d_in[1] = decision (unused by the forward math)
    const float* W = (const float*)d_in[2];
    const float* bias = (const float*)d_in[3];
    float* out = (float*)d_out;

    k_scores<<<(BB * TT) / 32, 256>>>(logits, W, bias);
    k_softmax<<<BB * OO, 256>>>();
    k_out<<<(BB * TT) / 32, 256>>>(logits, out);
}